// round 4
// baseline (speedup 1.0000x reference)
#include <cuda_runtime.h>

// Problem constants (fixed shapes for this dataset)
#define Nn 50000
#define Ee 600000

// ---------------- scratch (static __device__ — no allocation allowed) ----------------
__device__ int      g_is64;
__device__ int      g_src[Ee];
__device__ int      g_dst[Ee];
__device__ float    g_escale[Ee];
__device__ float    g_kj[(size_t)Ee * 128];     // x[src]+gate_embed
__device__ float    g_e256[(size_t)Ee * 256];   // KV (stage A) then M1 (stage B)
__device__ float    g_scores[(size_t)Ee * 4];
__device__ unsigned g_smax[Nn * 4];
__device__ float    g_ssum[Nn * 4];
__device__ float    g_Qn[Nn * 128];
__device__ float    g_agg[Nn * 128];
__device__ float    g_agg2[Nn * 128];
__device__ float    g_tmp[Nn * 128];
__device__ float    g_h[Nn * 128];
__device__ float    g_h2[Nn * 128];
__device__ float    g_hn[Nn * 128];
__device__ float    g_hff[Nn * 128];
__device__ float    g_G[Nn * 128];
__device__ float    g_Hd[Nn * 256];
__device__ float    g_Hs[Nn * 256];
__device__ float    g_cat[Nn * 256];
__device__ float    g_GU[Nn * 256];
__device__ float    g_cat2[Nn * 256];
__device__ float    g_F1[Nn * 512];
__device__ float    g_Wkv[128 * 256];
__device__ float    g_bkv[256];
__device__ float    g_Wgu[256 * 256];
__device__ float    g_bgu[256];

// ---------------- helpers ----------------
__device__ __forceinline__ float warp_sum32(float v) {
#pragma unroll
    for (int o = 16; o; o >>= 1) v += __shfl_xor_sync(0xffffffffu, v, o);
    return v;
}
__device__ __forceinline__ float gelu_f(float x) {
    return 0.5f * x * (1.0f + erff(x * 0.7071067811865476f));
}
__device__ __forceinline__ float sigm_f(float x) { return 1.0f / (1.0f + expf(-x)); }
// monotonic unsigned encoding of float for atomicMax
__device__ __forceinline__ unsigned fenc(float f) {
    unsigned u = __float_as_uint(f);
    return (u & 0x80000000u) ? ~u : (u | 0x80000000u);
}
__device__ __forceinline__ float fdec(unsigned e) {
    unsigned u = (e & 0x80000000u) ? (e & 0x7fffffffu) : ~e;
    return __uint_as_float(u);
}

// ---------------- generic 128x128x8 register-tiled fp32 GEMM ----------------
// C[M,Ncols] = A[M,K] @ W[K,Ncols] (+bias) (+activation)
// EPI: 0=store, 1=store(gelu), 2=store(sigmoid), 3=scaled scatter-atomicAdd by sidx
template <int EPI>
__global__ void __launch_bounds__(256) gemm_k(
    const float* __restrict__ A, const float* __restrict__ W,
    const float* __restrict__ bias, float* __restrict__ C,
    int M, int K, int Ncols,
    const int* __restrict__ sidx, const float* __restrict__ sscale)
{
    __shared__ float As[8][132];  // [k][m], padded
    __shared__ float Bs[8][132];  // [k][n], padded
    const int bm = blockIdx.x * 128;
    const int bn = blockIdx.y * 128;
    const int tid = threadIdx.x;
    const int ty = tid >> 4;           // 0..15 -> rows ty*8
    const int tx = tid & 15;           // 0..15 -> cols tx*8
    const int la_r = tid >> 1;         // A load: row within tile
    const int la_k = (tid & 1) << 2;   // A load: k offset (0 or 4)
    const int lb_k = tid >> 5;         // B load: k row
    const int lb_c = (tid & 31) << 2;  // B load: col offset

    float acc[8][8];
#pragma unroll
    for (int i = 0; i < 8; i++)
#pragma unroll
        for (int j = 0; j < 8; j++) acc[i][j] = 0.f;

    const int arow = bm + la_r;
    const bool aok = arow < M;
    const float* Aptr = A + (size_t)arow * K + la_k;
    const float* Wptr = W + (size_t)lb_k * Ncols + bn + lb_c;

    for (int k0 = 0; k0 < K; k0 += 8) {
        float4 av = make_float4(0.f, 0.f, 0.f, 0.f);
        if (aok) av = *reinterpret_cast<const float4*>(Aptr + k0);
        float4 bv = *reinterpret_cast<const float4*>(Wptr + (size_t)k0 * Ncols);
        __syncthreads();
        As[la_k + 0][la_r] = av.x;
        As[la_k + 1][la_r] = av.y;
        As[la_k + 2][la_r] = av.z;
        As[la_k + 3][la_r] = av.w;
        *reinterpret_cast<float4*>(&Bs[lb_k][lb_c]) = bv;
        __syncthreads();
#pragma unroll
        for (int kk = 0; kk < 8; kk++) {
            float a0[8], b0[8];
            *(float4*)(a0)     = *(const float4*)(&As[kk][ty * 8]);
            *(float4*)(a0 + 4) = *(const float4*)(&As[kk][ty * 8 + 4]);
            *(float4*)(b0)     = *(const float4*)(&Bs[kk][tx * 8]);
            *(float4*)(b0 + 4) = *(const float4*)(&Bs[kk][tx * 8 + 4]);
#pragma unroll
            for (int i = 0; i < 8; i++)
#pragma unroll
                for (int j = 0; j < 8; j++)
                    acc[i][j] = fmaf(a0[i], b0[j], acc[i][j]);
        }
    }

    float bj[8];
    if (bias) {
        *(float4*)(bj)     = *(const float4*)(bias + bn + tx * 8);
        *(float4*)(bj + 4) = *(const float4*)(bias + bn + tx * 8 + 4);
    } else {
#pragma unroll
        for (int j = 0; j < 8; j++) bj[j] = 0.f;
    }
#pragma unroll
    for (int i = 0; i < 8; i++) {
        int row = bm + ty * 8 + i;
        if (row >= M) continue;
        float v[8];
#pragma unroll
        for (int j = 0; j < 8; j++) {
            float t = acc[i][j] + bj[j];
            if (EPI == 1) t = gelu_f(t);
            if (EPI == 2) t = sigm_f(t);
            v[j] = t;
        }
        if (EPI == 3) {
            int node = sidx[row];
            float sc = sscale[row];
            float* dp = C + (size_t)node * Ncols + bn + tx * 8;
#pragma unroll
            for (int j = 0; j < 8; j++) atomicAdd(dp + j, v[j] * sc);
        } else {
            float* cp = C + (size_t)row * Ncols + bn + tx * 8;
            *(float4*)cp       = *(float4*)(v);
            *(float4*)(cp + 4) = *(float4*)(v + 4);
        }
    }
}

// ---------------- small kernels ----------------
__global__ void k_detect(const void* ei) {
    if (blockIdx.x == 0 && threadIdx.x == 0) {
        const long long* p = (const long long*)ei;
        int ok = 1;
        for (int i = 0; i < 64; i++) {
            long long v = p[i];
            if (v < 0 || v >= (long long)Nn) { ok = 0; break; }
        }
        g_is64 = ok;
    }
}

__global__ void k_convert(const void* ei) {
    int i = blockIdx.x * blockDim.x + threadIdx.x;
    if (i >= Ee) return;
    if (g_is64) {
        const long long* p = (const long long*)ei;
        g_src[i] = (int)p[i];
        g_dst[i] = (int)p[Ee + i];
    } else {
        const int* p = (const int*)ei;
        g_src[i] = p[i];
        g_dst[i] = p[Ee + i];
    }
}

__global__ void k_escale(const float* __restrict__ qd, const float* __restrict__ wd,
                         const float* __restrict__ bd) {
    int e = blockIdx.x * blockDim.x + threadIdx.x;
    if (e >= Ee) return;
    float q = qd[e];
    float s = 0.f;
#pragma unroll
    for (int h = 0; h < 4; h++) s += sigm_f(q * wd[h] + bd[h]);
    g_escale[e] = 1.f + 0.25f * s;
}

__global__ void k_zero(float* p, int n) {
    int i = blockIdx.x * blockDim.x + threadIdx.x;
    if (i < n) p[i] = 0.f;
}
__global__ void k_fillu(unsigned* p, int n, unsigned v) {
    int i = blockIdx.x * blockDim.x + threadIdx.x;
    if (i < n) p[i] = v;
}

__global__ void k_pack2(const float* __restrict__ A, const float* __restrict__ B,
                        float* __restrict__ out, int K, int nA, int nB) {
    int i = blockIdx.x * blockDim.x + threadIdx.x;
    int Wt = nA + nB;
    if (i >= K * Wt) return;
    int k = i / Wt, j = i - k * Wt;
    out[i] = (j < nA) ? A[k * nA + j] : B[k * nB + (j - nA)];
}

__global__ void k_build_kj(const float* __restrict__ x, const float* __restrict__ ge) {
    int i = blockIdx.x * blockDim.x + threadIdx.x;  // over Ee*32 float4s
    if (i >= Ee * 32) return;
    int e = i >> 5, c = i & 31;
    int src = g_src[e];
    float4 a = ((const float4*)x)[(size_t)src * 32 + c];
    float4 b = ((const float4*)ge)[(size_t)i];
    float4 r = make_float4(a.x + b.x, a.y + b.y, a.z + b.z, a.w + b.w);
    ((float4*)g_kj)[(size_t)i] = r;
}

// one warp per edge: per-head q.k + tanh temporal bias; atomicMax segment max
__global__ void k_scores(const float* __restrict__ tp, const float* __restrict__ wt,
                         const float* __restrict__ bt) {
    int e = blockIdx.x * 8 + (threadIdx.x >> 5);
    if (e >= Ee) return;
    int lane = threadIdx.x & 31;
    int h = lane >> 3, j = lane & 7;
    int dst = g_dst[e];
    float4 q = *(const float4*)(g_Qn + (size_t)dst * 128 + h * 32 + j * 4);
    float4 k = *(const float4*)(g_e256 + (size_t)e * 256 + h * 32 + j * 4);
    float d = q.x * k.x + q.y * k.y + q.z * k.z + q.w * k.w;
    d += __shfl_xor_sync(0xffffffffu, d, 1);
    d += __shfl_xor_sync(0xffffffffu, d, 2);
    d += __shfl_xor_sync(0xffffffffu, d, 4);
    if (j == 0) {
        float s = d * 0.17677669529663687f + tanhf(tp[e] * wt[h] + bt[h]);
        g_scores[(size_t)e * 4 + h] = s;
        atomicMax(&g_smax[dst * 4 + h], fenc(s));
    }
}

__global__ void k_expsum() {
    int i = blockIdx.x * blockDim.x + threadIdx.x;
    if (i >= Ee * 4) return;
    int e = i >> 2, h = i & 3;
    int dst = g_dst[e];
    float mx = fdec(g_smax[dst * 4 + h]);
    float ex = expf(g_scores[i] - mx);
    g_scores[i] = ex;
    atomicAdd(&g_ssum[dst * 4 + h], ex);
}

// one warp per edge: msg = attn*v, scatter-add into agg
__global__ void k_message() {
    int e = blockIdx.x * 8 + (threadIdx.x >> 5);
    if (e >= Ee) return;
    int lane = threadIdx.x & 31;
    int h = lane >> 3, j = lane & 7;
    int dst = g_dst[e];
    float attn = g_scores[(size_t)e * 4 + h] / g_ssum[dst * 4 + h];
    float4 v = *(const float4*)(g_e256 + (size_t)e * 256 + 128 + h * 32 + j * 4);
    float* o = g_agg + (size_t)dst * 128 + h * 32 + j * 4;
    atomicAdd(o + 0, attn * v.x);
    atomicAdd(o + 1, attn * v.y);
    atomicAdd(o + 2, attn * v.z);
    atomicAdd(o + 3, attn * v.w);
}

// out = LN(a + b), one warp per 128-wide row
__global__ void k_ln_add(const float* __restrict__ a, const float* __restrict__ b,
                         float* __restrict__ out) {
    int n = blockIdx.x * 8 + (threadIdx.x >> 5);
    if (n >= Nn) return;
    int lane = threadIdx.x & 31;
    float4 va = ((const float4*)a)[(size_t)n * 32 + lane];
    float4 vb = ((const float4*)b)[(size_t)n * 32 + lane];
    float4 p = make_float4(va.x + vb.x, va.y + vb.y, va.z + vb.z, va.w + vb.w);
    float s = warp_sum32(p.x + p.y + p.z + p.w);
    float sq = warp_sum32(p.x * p.x + p.y * p.y + p.z * p.z + p.w * p.w);
    float m = s * (1.f / 128.f);
    float var = sq * (1.f / 128.f) - m * m;
    float inv = rsqrtf(var + 1e-5f);
    float4 r = make_float4((p.x - m) * inv, (p.y - m) * inv, (p.z - m) * inv, (p.w - m) * inv);
    ((float4*)out)[(size_t)n * 32 + lane] = r;
}

// M1[e] = gelu(M1[e] + Hd[dst] + Hs[src] + bm1), one warp per edge (256 cols)
__global__ void k_m1(const float* __restrict__ bm1) {
    int e = blockIdx.x * 8 + (threadIdx.x >> 5);
    if (e >= Ee) return;
    int lane = threadIdx.x & 31;
    int dst = g_dst[e], src = g_src[e];
    float4* M4 = (float4*)g_e256;
    const float4* D4 = (const float4*)g_Hd;
    const float4* S4 = (const float4*)g_Hs;
    const float4* B4 = (const float4*)bm1;
#pragma unroll
    for (int t = 0; t < 2; t++) {
        int c = lane + 32 * t;
        float4 v = M4[(size_t)e * 64 + c];
        float4 d = D4[(size_t)dst * 64 + c];
        float4 s = S4[(size_t)src * 64 + c];
        float4 b = B4[c];
        v.x = gelu_f(v.x + d.x + s.x + b.x);
        v.y = gelu_f(v.y + d.y + s.y + b.y);
        v.z = gelu_f(v.z + d.z + s.z + b.z);
        v.w = gelu_f(v.w + d.w + s.w + b.w);
        M4[(size_t)e * 64 + c] = v;
    }
}

// out[N,256] = [a | b]
__global__ void k_concat(const float* __restrict__ a, const float* __restrict__ b,
                         float* __restrict__ out) {
    int i = blockIdx.x * blockDim.x + threadIdx.x;
    if (i >= Nn * 64) return;
    int n = i >> 6, c = i & 63;
    float4 v = (c < 32) ? ((const float4*)a)[(size_t)n * 32 + c]
                        : ((const float4*)b)[(size_t)n * 32 + (c - 32)];
    ((float4*)out)[(size_t)i] = v;
}

// stage-B combine: g=sigmoid(GU[:,:128]), u=gelu(GU[:,128:]); h2=LN(h*(1-g)+u*g); hn=LN(h2)
__global__ void k_combine() {
    int n = blockIdx.x * 8 + (threadIdx.x >> 5);
    if (n >= Nn) return;
    int lane = threadIdx.x & 31;
    const float4* GU4 = (const float4*)g_GU;
    float4 gv = GU4[(size_t)n * 64 + lane];
    float4 uv = GU4[(size_t)n * 64 + 32 + lane];
    float4 hv = ((const float4*)g_h)[(size_t)n * 32 + lane];
    float gx = sigm_f(gv.x), gy = sigm_f(gv.y), gz = sigm_f(gv.z), gw = sigm_f(gv.w);
    float ux = gelu_f(uv.x), uy = gelu_f(uv.y), uz = gelu_f(uv.z), uw = gelu_f(uv.w);
    float4 p;
    p.x = hv.x * (1.f - gx) + ux * gx;
    p.y = hv.y * (1.f - gy) + uy * gy;
    p.z = hv.z * (1.f - gz) + uz * gz;
    p.w = hv.w * (1.f - gw) + uw * gw;
    // LN1
    float s = warp_sum32(p.x + p.y + p.z + p.w);
    float sq = warp_sum32(p.x * p.x + p.y * p.y + p.z * p.z + p.w * p.w);
    float m = s * (1.f / 128.f);
    float var = sq * (1.f / 128.f) - m * m;
    float inv = rsqrtf(var + 1e-5f);
    float4 h2 = make_float4((p.x - m) * inv, (p.y - m) * inv, (p.z - m) * inv, (p.w - m) * inv);
    ((float4*)g_h2)[(size_t)n * 32 + lane] = h2;
    // LN2
    float s2 = warp_sum32(h2.x + h2.y + h2.z + h2.w);
    float sq2 = warp_sum32(h2.x * h2.x + h2.y * h2.y + h2.z * h2.z + h2.w * h2.w);
    float m2 = s2 * (1.f / 128.f);
    float var2 = sq2 * (1.f / 128.f) - m2 * m2;
    float inv2 = rsqrtf(var2 + 1e-5f);
    float4 hn = make_float4((h2.x - m2) * inv2, (h2.y - m2) * inv2,
                            (h2.z - m2) * inv2, (h2.w - m2) * inv2);
    ((float4*)g_hn)[(size_t)n * 32 + lane] = hn;
}

// out = LN(h2 + G*hff)
__global__ void k_final(float* __restrict__ out) {
    int n = blockIdx.x * 8 + (threadIdx.x >> 5);
    if (n >= Nn) return;
    int lane = threadIdx.x & 31;
    float4 a = ((const float4*)g_h2)[(size_t)n * 32 + lane];
    float4 g = ((const float4*)g_G)[(size_t)n * 32 + lane];
    float4 f = ((const float4*)g_hff)[(size_t)n * 32 + lane];
    float4 p = make_float4(a.x + g.x * f.x, a.y + g.y * f.y, a.z + g.z * f.z, a.w + g.w * f.w);
    float s = warp_sum32(p.x + p.y + p.z + p.w);
    float sq = warp_sum32(p.x * p.x + p.y * p.y + p.z * p.z + p.w * p.w);
    float m = s * (1.f / 128.f);
    float var = sq * (1.f / 128.f) - m * m;
    float inv = rsqrtf(var + 1e-5f);
    float4 r = make_float4((p.x - m) * inv, (p.y - m) * inv, (p.z - m) * inv, (p.w - m) * inv);
    ((float4*)out)[(size_t)n * 32 + lane] = r;
}

// ---------------- launch ----------------
static inline int cdiv_i(int a, int b) { return (a + b - 1) / b; }

extern "C" void kernel_launch(void* const* d_in, const int* in_sizes, int n_in,
                              void* d_out, int out_size) {
    (void)in_sizes; (void)n_in; (void)out_size;
    const float* x    = (const float*)d_in[0];
    const void*  ei   = d_in[1];
    const float* ge   = (const float*)d_in[2];
    const float* tp   = (const float*)d_in[3];
    const float* qd   = (const float*)d_in[4];
    const float* Wq   = (const float*)d_in[5];  const float* bq   = (const float*)d_in[6];
    const float* Wk   = (const float*)d_in[7];  const float* bk   = (const float*)d_in[8];
    const float* Wv   = (const float*)d_in[9];  const float* bv   = (const float*)d_in[10];
    const float* wt   = (const float*)d_in[11]; const float* bt   = (const float*)d_in[12];
    const float* Wo   = (const float*)d_in[13]; const float* bo   = (const float*)d_in[14];
    const float* Wm1  = (const float*)d_in[15]; const float* bm1  = (const float*)d_in[16];
    const float* Wm2  = (const float*)d_in[17]; const float* bm2  = (const float*)d_in[18];
    const float* wd   = (const float*)d_in[19]; const float* bd   = (const float*)d_in[20];
    const float* Wg   = (const float*)d_in[21]; const float* bg   = (const float*)d_in[22];
    const float* Wu   = (const float*)d_in[23]; const float* bu   = (const float*)d_in[24];
    const float* Wf1  = (const float*)d_in[25]; const float* bf1  = (const float*)d_in[26];
    const float* Wf2  = (const float*)d_in[27]; const float* bf2  = (const float*)d_in[28];
    const float* Wgate= (const float*)d_in[29]; const float* bgate= (const float*)d_in[30];

    // symbol addresses (pure lookups; capture-safe, no allocation)
    void* pv;
    float *p_Qn, *p_kj, *p_e256, *p_agg, *p_agg2, *p_tmp, *p_h, *p_h2, *p_hn, *p_hff, *p_G;
    float *p_Hd, *p_Hs, *p_cat, *p_GU, *p_cat2, *p_F1, *p_Wkv, *p_bkv, *p_Wgu, *p_bgu, *p_ssum, *p_escale;
    unsigned* p_smax; int* p_dst;
    cudaGetSymbolAddress(&pv, g_Qn);     p_Qn    = (float*)pv;
    cudaGetSymbolAddress(&pv, g_kj);     p_kj    = (float*)pv;
    cudaGetSymbolAddress(&pv, g_e256);   p_e256  = (float*)pv;
    cudaGetSymbolAddress(&pv, g_agg);    p_agg   = (float*)pv;
    cudaGetSymbolAddress(&pv, g_agg2);   p_agg2  = (float*)pv;
    cudaGetSymbolAddress(&pv, g_tmp);    p_tmp   = (float*)pv;
    cudaGetSymbolAddress(&pv, g_h);      p_h     = (float*)pv;
    cudaGetSymbolAddress(&pv, g_h2);     p_h2    = (float*)pv;
    cudaGetSymbolAddress(&pv, g_hn);     p_hn    = (float*)pv;
    cudaGetSymbolAddress(&pv, g_hff);    p_hff   = (float*)pv;
    cudaGetSymbolAddress(&pv, g_G);      p_G     = (float*)pv;
    cudaGetSymbolAddress(&pv, g_Hd);     p_Hd    = (float*)pv;
    cudaGetSymbolAddress(&pv, g_Hs);     p_Hs    = (float*)pv;
    cudaGetSymbolAddress(&pv, g_cat);    p_cat   = (float*)pv;
    cudaGetSymbolAddress(&pv, g_GU);     p_GU    = (float*)pv;
    cudaGetSymbolAddress(&pv, g_cat2);   p_cat2  = (float*)pv;
    cudaGetSymbolAddress(&pv, g_F1);     p_F1    = (float*)pv;
    cudaGetSymbolAddress(&pv, g_Wkv);    p_Wkv   = (float*)pv;
    cudaGetSymbolAddress(&pv, g_bkv);    p_bkv   = (float*)pv;
    cudaGetSymbolAddress(&pv, g_Wgu);    p_Wgu   = (float*)pv;
    cudaGetSymbolAddress(&pv, g_bgu);    p_bgu   = (float*)pv;
    cudaGetSymbolAddress(&pv, g_ssum);   p_ssum  = (float*)pv;
    cudaGetSymbolAddress(&pv, g_escale); p_escale= (float*)pv;
    cudaGetSymbolAddress(&pv, g_smax);   p_smax  = (unsigned*)pv;
    cudaGetSymbolAddress(&pv, g_dst);    p_dst   = (int*)pv;

    const int TB = 256;

    // --- prep ---
    k_detect<<<1, 1>>>(ei);
    k_convert<<<cdiv_i(Ee, TB), TB>>>(ei);
    k_escale<<<cdiv_i(Ee, TB), TB>>>(qd, wd, bd);
    k_zero<<<cdiv_i(Nn * 128, TB), TB>>>(p_agg, Nn * 128);
    k_zero<<<cdiv_i(Nn * 128, TB), TB>>>(p_agg2, Nn * 128);
    k_zero<<<cdiv_i(Nn * 4, TB), TB>>>(p_ssum, Nn * 4);
    k_fillu<<<cdiv_i(Nn * 4, TB), TB>>>(p_smax, Nn * 4, 0x007FFFFFu);  // enc(-inf)
    k_pack2<<<cdiv_i(128 * 256, TB), TB>>>(Wk, Wv, p_Wkv, 128, 128, 128);
    k_pack2<<<cdiv_i(256, TB), TB>>>(bk, bv, p_bkv, 1, 128, 128);
    k_pack2<<<cdiv_i(256 * 256, TB), TB>>>(Wg, Wu, p_Wgu, 256, 128, 128);
    k_pack2<<<cdiv_i(256, TB), TB>>>(bg, bu, p_bgu, 1, 128, 128);

    // --- stage A: causal temporal attention ---
    gemm_k<0><<<dim3(cdiv_i(Nn, 128), 1), 256>>>(x, Wq, bq, p_Qn, Nn, 128, 128, nullptr, nullptr);
    k_build_kj<<<cdiv_i(Ee * 32, TB), TB>>>(x, ge);
    gemm_k<0><<<dim3(cdiv_i(Ee, 128), 2), 256>>>(p_kj, p_Wkv, p_bkv, p_e256, Ee, 128, 256, nullptr, nullptr);
    k_scores<<<cdiv_i(Ee, 8), 256>>>(tp, wt, bt);
    k_expsum<<<cdiv_i(Ee * 4, TB), TB>>>();
    k_message<<<cdiv_i(Ee, 8), 256>>>();
    gemm_k<0><<<dim3(cdiv_i(Nn, 128), 1), 256>>>(p_agg, Wo, bo, p_tmp, Nn, 128, 128, nullptr, nullptr);
    k_ln_add<<<cdiv_i(Nn, 8), 256>>>(x, p_tmp, p_h);

    // --- stage B: entanglement-aware conv ---
    gemm_k<0><<<dim3(cdiv_i(Nn, 128), 2), 256>>>(p_h, Wm1,              nullptr, p_Hd, Nn, 128, 256, nullptr, nullptr);
    gemm_k<0><<<dim3(cdiv_i(Nn, 128), 2), 256>>>(p_h, Wm1 + 128 * 256,  nullptr, p_Hs, Nn, 128, 256, nullptr, nullptr);
    gemm_k<0><<<dim3(cdiv_i(Ee, 128), 2), 256>>>(ge,  Wm1 + 256 * 256,  nullptr, p_e256, Ee, 128, 256, nullptr, nullptr);
    k_m1<<<cdiv_i(Ee, 8), 256>>>(bm1);
    gemm_k<3><<<dim3(cdiv_i(Ee, 128), 1), 256>>>(p_e256, Wm2, bm2, p_agg2, Ee, 256, 128, p_dst, p_escale);
    k_concat<<<cdiv_i(Nn * 64, TB), TB>>>(p_h, p_agg2, p_cat);
    gemm_k<0><<<dim3(cdiv_i(Nn, 128), 2), 256>>>(p_cat, p_Wgu, p_bgu, p_GU, Nn, 256, 256, nullptr, nullptr);
    k_combine<<<cdiv_i(Nn, 8), 256>>>();

    // --- stage C: FF + gated residual ---
    gemm_k<1><<<dim3(cdiv_i(Nn, 128), 4), 256>>>(p_hn, Wf1, bf1, p_F1, Nn, 128, 512, nullptr, nullptr);
    gemm_k<0><<<dim3(cdiv_i(Nn, 128), 1), 256>>>(p_F1, Wf2, bf2, p_hff, Nn, 512, 128, nullptr, nullptr);
    k_concat<<<cdiv_i(Nn * 64, TB), TB>>>(p_h2, p_hff, p_cat2);
    gemm_k<2><<<dim3(cdiv_i(Nn, 128), 1), 256>>>(p_cat2, Wgate, bgate, p_G, Nn, 256, 128, nullptr, nullptr);
    k_final<<<cdiv_i(Nn, 8), 256>>>((float*)d_out);
}